// round 5
// baseline (speedup 1.0000x reference)
#include <cuda_runtime.h>

// Problem dims
static constexpr int Bn = 32, Tn = 10, Dn = 10, Un = 50, Pn = 50, En = 256;
static constexpr int Rr = 64;    // padded row count (U and P padded to 64)
static constexpr int SA = 260;   // row stride (floats) for X/K/V/H tiles (pad vs 256 for banking)
static constexpr int SSs = 68;   // row stride for score tile (64 cols + pad)
static constexpr int SWs = 264;  // stride for staged weight tile [32 k][256 n]

static constexpr int SMEM_FLOATS = 3 * Rr * SA + Rr * SSs;   // 49920 + 4352 = 54272
static constexpr int SMEM_BYTES  = SMEM_FLOATS * 4;          // 217088 B

// ---- packed f32x2 helpers (Blackwell FFMA2 — PTX-only path) ----
__device__ __forceinline__ unsigned long long pk2(float lo, float hi) {
    unsigned long long r;
    asm("mov.b64 %0, {%1, %2};" : "=l"(r) : "f"(lo), "f"(hi));
    return r;
}
__device__ __forceinline__ void fma2(unsigned long long &acc, unsigned long long a, unsigned long long b) {
    asm("fma.rn.f32x2 %0, %1, %2, %0;" : "+l"(acc) : "l"(a), "l"(b));
}
__device__ __forceinline__ float2 upk(unsigned long long v) {
    float lo, hi;
    asm("mov.b64 {%0, %1}, %2;" : "=f"(lo), "=f"(hi) : "l"(v));
    return make_float2(lo, hi);
}
__device__ __forceinline__ float wsum(float v) {
#pragma unroll
    for (int o = 16; o > 0; o >>= 1) v += __shfl_xor_sync(0xffffffffu, v, o);
    return v;
}
__device__ __forceinline__ float wmax(float v) {
#pragma unroll
    for (int o = 16; o > 0; o >>= 1) v = fmaxf(v, __shfl_xor_sync(0xffffffffu, v, o));
    return v;
}

// C[64][256] += A[64][K=256] * W^T, W global [256 n][256 k] row-major.
// W staged into sW (transposed [k][n]) in 8 chunks of 32 k.
// Thread (tr = warp, tc = lane) owns rows tr*8..+7, cols tc*8..+7, packed acc[8][4].
__device__ __forceinline__ void ffn_gemm(
    const float* __restrict__ Wg, const float* __restrict__ sA, float* __restrict__ sW,
    unsigned long long acc[8][4], int tid, int tr, int tc)
{
    for (int c = 0; c < 8; ++c) {
        __syncthreads();           // previous chunk fully consumed / prior phase done
        // stage W chunk transposed: sW[k][n] = W[n][c*32 + k]
#pragma unroll
        for (int i = 0; i < 8; ++i) {
            int f  = tid + i * 256;       // 0..2047
            int n  = f >> 3;              // 0..255
            int k4 = f & 7;               // float4 index within 32-k chunk
            float4 w = *reinterpret_cast<const float4*>(Wg + n * En + c * 32 + k4 * 4);
            sW[(k4 * 4 + 0) * SWs + n] = w.x;
            sW[(k4 * 4 + 1) * SWs + n] = w.y;
            sW[(k4 * 4 + 2) * SWs + n] = w.z;
            sW[(k4 * 4 + 3) * SWs + n] = w.w;
        }
        __syncthreads();
#pragma unroll 4
        for (int kk = 0; kk < 32; ++kk) {
            float4 b0 = *reinterpret_cast<const float4*>(&sW[kk * SWs + tc * 8]);
            float4 b1 = *reinterpret_cast<const float4*>(&sW[kk * SWs + tc * 8 + 4]);
            unsigned long long w0 = pk2(b0.x, b0.y), w1 = pk2(b0.z, b0.w);
            unsigned long long w2 = pk2(b1.x, b1.y), w3 = pk2(b1.z, b1.w);
#pragma unroll
            for (int i = 0; i < 8; ++i) {
                float a = sA[(tr * 8 + i) * SA + c * 32 + kk];   // warp-broadcast LDS
                unsigned long long aa = pk2(a, a);
                fma2(acc[i][0], aa, w0);
                fma2(acc[i][1], aa, w1);
                fma2(acc[i][2], aa, w2);
                fma2(acc[i][3], aa, w3);
            }
        }
    }
}

__global__ __launch_bounds__(256, 1)
void fusion_block_kernel(
    const float* __restrict__ Qg_, const float* __restrict__ Kg_,
    const float* __restrict__ Vg_, const float* __restrict__ Mg_,
    const float* __restrict__ W1, const float* __restrict__ b1,
    const float* __restrict__ W2, const float* __restrict__ b2,
    const float* __restrict__ ln1w, const float* __restrict__ ln1b,
    const float* __restrict__ ln2w, const float* __restrict__ ln2b,
    float* __restrict__ Out)
{
    extern __shared__ float sm[];
    float* sX = sm;                 // Q tile -> x (LN1 out) [64][SA]
    float* sK = sm + Rr * SA;       // K tile -> H (ffn hidden) [64][SA]
    float* sV = sm + 2 * Rr * SA;   // V tile -> staged W chunks [32][SWs]
    float* sS = sm + 3 * Rr * SA;   // scores [64][SSs]

    const int tid  = threadIdx.x;
    const int warp = tid >> 5;
    const int lane = tid & 31;

    const int bid = blockIdx.x;         // enumerates (b, t, d)
    const int bt  = bid / Dn;           // b*T + t
    const int d   = bid - bt * Dn;
    const int b   = bt / Tn;
    const int bd  = b * Dn + d;

    const float* Qg = Qg_ + (size_t)bt  * (Un * En);
    const float* Kg = Kg_ + (size_t)bd  * (Pn * En);
    const float* Vg = Vg_ + (size_t)bd  * (Pn * En);
    const float* Mg = Mg_ + (size_t)bid * (Un * Pn);
    float*       Og = Out + (size_t)bid * (Un * En);

    // ---- Load Q/K/V tiles (rows >= 50 zero-padded) ----
    for (int f = tid; f < Rr * (En / 4); f += 256) {
        int row = f >> 6;
        int c4  = (f & 63) << 2;
        float4 z = make_float4(0.f, 0.f, 0.f, 0.f);
        float4 q = z, k = z, v = z;
        if (row < Un) {
            q = *reinterpret_cast<const float4*>(Qg + row * En + c4);
            k = *reinterpret_cast<const float4*>(Kg + row * En + c4);
            v = *reinterpret_cast<const float4*>(Vg + row * En + c4);
        }
        *reinterpret_cast<float4*>(&sX[row * SA + c4]) = q;
        *reinterpret_cast<float4*>(&sK[row * SA + c4]) = k;
        *reinterpret_cast<float4*>(&sV[row * SA + c4]) = v;
    }
    __syncthreads();

    // ---- S = Q K^T / scale + mask  (64x64, lanes own 2 u-rows, warps own 8 p-cols) ----
    {
        const int u0 = lane * 2;
        unsigned long long acc[2][8] = {};
#pragma unroll 4
        for (int e4 = 0; e4 < En / 4; ++e4) {
            float4 q0 = *reinterpret_cast<const float4*>(&sX[u0 * SA + e4 * 4]);
            float4 q1 = *reinterpret_cast<const float4*>(&sX[(u0 + 1) * SA + e4 * 4]);
            unsigned long long q0a = pk2(q0.x, q0.y), q0b = pk2(q0.z, q0.w);
            unsigned long long q1a = pk2(q1.x, q1.y), q1b = pk2(q1.z, q1.w);
#pragma unroll
            for (int j = 0; j < 8; ++j) {
                float4 kv = *reinterpret_cast<const float4*>(&sK[(warp * 8 + j) * SA + e4 * 4]);
                unsigned long long ka = pk2(kv.x, kv.y), kb = pk2(kv.z, kv.w);
                fma2(acc[0][j], q0a, ka); fma2(acc[0][j], q0b, kb);
                fma2(acc[1][j], q1a, ka); fma2(acc[1][j], q1b, kb);
            }
        }
        // sqrt(256) + 1e-8 rounds to exactly 16.0f in fp32
        const float inv_scale = 1.0f / 16.0f;
#pragma unroll
        for (int i = 0; i < 2; ++i) {
            int u = u0 + i;
#pragma unroll
            for (int j = 0; j < 8; ++j) {
                float2 pv = upk(acc[i][j]);
                float s = (pv.x + pv.y) * inv_scale;
                int p = warp * 8 + j;
                if (u < Un && p < Pn) s += Mg[u * Pn + p];
                sS[u * SSs + p] = s;
            }
        }
    }
    __syncthreads();

    // ---- softmax over p (valid p < 50), zeros in pad cols ----
    {
#pragma unroll
        for (int r = 0; r < 8; ++r) {
            int row = warp * 8 + r;
            float v0 = sS[row * SSs + lane];                                   // p = lane < 50 always
            float v1 = (lane + 32 < Pn) ? sS[row * SSs + lane + 32] : -1e30f;  // p = lane+32
            float m  = wmax(fmaxf(v0, v1));
            float e0 = __expf(v0 - m);
            float e1 = (lane + 32 < Pn) ? __expf(v1 - m) : 0.f;
            float inv = 1.f / wsum(e0 + e1);
            sS[row * SSs + lane]      = e0 * inv;
            sS[row * SSs + lane + 32] = e1 * inv;   // 0 for p >= 50
        }
    }
    __syncthreads();

    const int tr = warp;   // row group (8 rows)
    const int tc = lane;   // col group (8 cols)

    // ---- v_att = S @ V ;  x = Q + v_att (in place in sX) ----
    {
        unsigned long long acc[8][4] = {};
#pragma unroll 2
        for (int k = 0; k < Rr; ++k) {
            float4 b0 = *reinterpret_cast<const float4*>(&sV[k * SA + tc * 8]);
            float4 b1 = *reinterpret_cast<const float4*>(&sV[k * SA + tc * 8 + 4]);
            unsigned long long w0 = pk2(b0.x, b0.y), w1 = pk2(b0.z, b0.w);
            unsigned long long w2 = pk2(b1.x, b1.y), w3 = pk2(b1.z, b1.w);
#pragma unroll
            for (int i = 0; i < 8; ++i) {
                float a = sS[(tr * 8 + i) * SSs + k];
                unsigned long long aa = pk2(a, a);
                fma2(acc[i][0], aa, w0); fma2(acc[i][1], aa, w1);
                fma2(acc[i][2], aa, w2); fma2(acc[i][3], aa, w3);
            }
        }
#pragma unroll
        for (int i = 0; i < 8; ++i) {
            float* xp = &sX[(tr * 8 + i) * SA + tc * 8];
#pragma unroll
            for (int j2 = 0; j2 < 4; ++j2) {
                float2 v = upk(acc[i][j2]);
                xp[j2 * 2]     += v.x;
                xp[j2 * 2 + 1] += v.y;
            }
        }
    }
    __syncthreads();

    // ---- LN1 (one warp per row, 8 rows per warp) ----
    {
#pragma unroll
        for (int r = 0; r < 8; ++r) {
            int row = warp * 8 + r;
            float xv[8];
            float s = 0.f;
#pragma unroll
            for (int kk = 0; kk < 8; ++kk) { xv[kk] = sX[row * SA + lane + kk * 32]; s += xv[kk]; }
            float mu = wsum(s) * (1.f / En);
            float vs = 0.f;
#pragma unroll
            for (int kk = 0; kk < 8; ++kk) { float t = xv[kk] - mu; vs += t * t; }
            float rstd = rsqrtf(wsum(vs) * (1.f / En) + 1e-5f);
#pragma unroll
            for (int kk = 0; kk < 8; ++kk) {
                int col = lane + kk * 32;
                sX[row * SA + col] = (xv[kk] - mu) * rstd * ln1w[col] + ln1b[col];
            }
        }
    }
    __syncthreads();

    // ---- FFN layer 1: H = relu(x @ W1^T + b1) -> sK ----
    {
        unsigned long long acc[8][4] = {};
        ffn_gemm(W1, sX, sV, acc, tid, tr, tc);
#pragma unroll
        for (int i = 0; i < 8; ++i) {
            int row = tr * 8 + i;
#pragma unroll
            for (int j2 = 0; j2 < 4; ++j2) {
                float2 v = upk(acc[i][j2]);
                int col = tc * 8 + j2 * 2;
                sK[row * SA + col]     = fmaxf(v.x + b1[col], 0.f);
                sK[row * SA + col + 1] = fmaxf(v.y + b1[col + 1], 0.f);
            }
        }
    }
    // (first __syncthreads inside next ffn_gemm separates H writes from W2 staging)

    // ---- FFN layer 2: y = H @ W2^T + b2 + x (in place into sX) ----
    {
        unsigned long long acc[8][4] = {};
        ffn_gemm(W2, sK, sV, acc, tid, tr, tc);
#pragma unroll
        for (int i = 0; i < 8; ++i) {
            int row = tr * 8 + i;
#pragma unroll
            for (int j2 = 0; j2 < 4; ++j2) {
                float2 v = upk(acc[i][j2]);
                int col = tc * 8 + j2 * 2;
                sX[row * SA + col]     += v.x + b2[col];
                sX[row * SA + col + 1] += v.y + b2[col + 1];
            }
        }
    }
    __syncthreads();

    // ---- LN2 + store (valid rows only) ----
    {
#pragma unroll
        for (int r = 0; r < 8; ++r) {
            int row = warp * 8 + r;
            if (row >= Un) break;    // uniform per warp
            float xv[8];
            float s = 0.f;
#pragma unroll
            for (int kk = 0; kk < 8; ++kk) { xv[kk] = sX[row * SA + lane + kk * 32]; s += xv[kk]; }
            float mu = wsum(s) * (1.f / En);
            float vs = 0.f;
#pragma unroll
            for (int kk = 0; kk < 8; ++kk) { float t = xv[kk] - mu; vs += t * t; }
            float rstd = rsqrtf(wsum(vs) * (1.f / En) + 1e-5f);
#pragma unroll
            for (int kk = 0; kk < 8; ++kk) {
                int col = lane + kk * 32;
                Og[row * En + col] = (xv[kk] - mu) * rstd * ln2w[col] + ln2b[col];
            }
        }
    }
}

extern "C" void kernel_launch(void* const* d_in, const int* in_sizes, int n_in,
                              void* d_out, int out_size) {
    (void)in_sizes; (void)n_in; (void)out_size;
    cudaFuncSetAttribute(fusion_block_kernel,
                         cudaFuncAttributeMaxDynamicSharedMemorySize, SMEM_BYTES);
    fusion_block_kernel<<<Bn * Tn * Dn, 256, SMEM_BYTES>>>(
        (const float*)d_in[0],  // Q
        (const float*)d_in[1],  // K
        (const float*)d_in[2],  // V
        (const float*)d_in[3],  // attention_mask
        (const float*)d_in[4],  // W1
        (const float*)d_in[5],  // b1
        (const float*)d_in[6],  // W2
        (const float*)d_in[7],  // b2
        (const float*)d_in[8],  // ln1_w
        (const float*)d_in[9],  // ln1_b
        (const float*)d_in[10], // ln2_w
        (const float*)d_in[11], // ln2_b
        (float*)d_out);
}